// round 14
// baseline (speedup 1.0000x reference)
#include <cuda_runtime.h>
#include <math.h>

#define PI_D 3.14159265358979323846
#define SC1V 0.03872983346207417f   /* 1/sqrt(2000/3) */
#define SC2V 0.06324555320336759f   /* 1/sqrt(250)    */

typedef unsigned long long u64;

// packed f32x2 helpers
__device__ __forceinline__ float2 u2f(u64 v){ float2 r; asm("mov.b64 {%0,%1}, %2;":"=f"(r.x),"=f"(r.y):"l"(v)); return r; }
__device__ __forceinline__ u64 pk2(float a, float b){ u64 r; asm("mov.b64 %0, {%1,%2};":"=l"(r):"f"(a),"f"(b)); return r; }
__device__ __forceinline__ void fma2(u64 &acc, u64 a, u64 b){
    asm("fma.rn.f32x2 %0, %1, %2, %3;" : "=l"(acc) : "l"(a), "l"(b), "l"(acc));
}

// ---------------- constant tables (device-computed) ----------------
__device__ float  c_d1[10][60][19];
__device__ float  c_dh1[10][19];
__device__ float  c_dinv1p[10][20][19][10];
__device__ float  c_d2[5][20][9][9];
__device__ float  c_dh2[5][9][9];
__device__ float  c_dinv2[5][10][9][9];
__device__ float  c_w5[10];
__device__ float2 c_tw60[19][60];                 // e^{-2pi i m p/60}
__device__ float2 c_tw20b[19][20];                // e^{+2pi i m j/20}
__device__ float2 c_tw20br[19][20];               // rotated (-y,x)
__device__ __align__(16) float2 c_tw20f[9][20];   // e^{-2pi i m k/20}
__device__ __align__(16) float2 c_tw20fr[9][20];  // rotated
__device__ float2 c_tw10b[9][10];                 // e^{+2pi i m j/10}
__device__ float2 c_tw10br[9][10];                // rotated

__constant__ double c_fct[20] = {1.,1.,2.,6.,24.,120.,720.,5040.,40320.,362880.,
    3628800.,39916800.,479001600.,6227020800.,87178291200.,1307674368000.,
    20922789888000.,355687428096000.,6402373705728000.,121645100408832000.};

// ---------------- scratch ----------------
__device__ float2 g_xfT[19][60][32];
__device__ float2 g_kfc[100][19];
__device__ __align__(16) float2 g_Kp[100][20][10];   // [i][k][n]  (n contiguous)
__device__ float2 g_G[10][32][20][20];
__device__ float2 g_xg[32][100][20][81];
__device__ float2 g_k2f[9][100][200];
__device__ float2 g_T2[5][41][32][100];
__device__ float2 g_z2t[32][200][405];

// ---------------- Wigner-d from precomputed half-angle cos/sin ----------------
__device__ double dev_wigner_cs(int l, int m, int n, double cb, double sb, const double* ifct){
    double pref = sqrt(c_fct[l+m]*c_fct[l-m]*c_fct[l+n]*c_fct[l-n]);
    int s0 = (n-m > 0) ? (n-m) : 0;
    int s1 = (l+n < l-m) ? (l+n) : (l-m);
    if(s1 < s0) return 0.0;
    int e0 = 2*l+n-m-2*s0, f0 = m-n+2*s0;
    double cbe = 1.0; for(int i=0;i<e0;i++) cbe *= cb;
    double sbf = 1.0; for(int i=0;i<f0;i++) sbf *= sb;
    double r  = (sb*sb)/(cb*cb);
    double pw = cbe*sbf;
    double acc = 0.0;
    for(int s=s0;s<=s1;s++){
        double deni = ifct[l+n-s]*ifct[s]*ifct[m-n+s]*ifct[l-m-s];
        double sg   = ((m-n+s)&1) ? -1.0 : 1.0;
        acc += sg*pw*deni;
        pw *= r;
    }
    return pref*acc;
}

__device__ double dev_qw(int b, int j){
    double beta = PI_D*(2*j+1)/(4.0*b);
    double s=0.0;
    for(int k=1;k<2*b;k+=2) s += sin(k*beta)/(double)k;
    return 2.0/b*sin(beta)*s;
}

// ---------------- init: output reset + per-block smem weights + all tables ----------------
__global__ void k_init(const float* __restrict__ bl, float* __restrict__ out){
    {
        int gi = blockIdx.x*blockDim.x + threadIdx.x;
        if(gi < 320) out[gi] = bl[gi%10];
    }
    __shared__ double s_w30[60], s_w10[20];
    __shared__ float  s_w5f[10];
    __shared__ double cb120[60], sb120[60], cb40[20], sb40[20], cb20[10], sb20[10];
    __shared__ double s_ifct[20];
    int tt = threadIdx.x;
    if(tt < 60){ s_w30[tt]=dev_qw(30,tt); double a=PI_D*(2*tt+1)/240.0; cb120[tt]=cos(a); sb120[tt]=sin(a); }
    else if(tt < 80){ int z=tt-60; s_w10[z]=dev_qw(10,z); double a=PI_D*(2*z+1)/80.0; cb40[z]=cos(a); sb40[z]=sin(a); }
    else if(tt < 90){ int z=tt-80; s_w5f[z]=(float)dev_qw(5,z); double a=PI_D*(2*z+1)/40.0; cb20[z]=cos(a); sb20[z]=sin(a); }
    else if(tt < 110){ s_ifct[tt-90] = 1.0/c_fct[tt-90]; }
    __syncthreads();
    const double cbh = 0.70710678118654752, sbh = 0.70710678118654752;
    const int total = 11400+190+38000+8100+405+4050+1140+380+180+90+10;
    for(int idx = blockIdx.x*blockDim.x+threadIdx.x; idx<total; idx += gridDim.x*blockDim.x){
        int t = idx;
        if(t < 11400){ int l=t/1140, r=t%1140, z=r/19, mm=r%19, m=mm-9;
            c_d1[l][z][mm] = (abs(m)<=l) ? (float)(dev_wigner_cs(l,m,0,cb120[z],sb120[z],s_ifct)*s_w30[z]) : 0.f;
            continue; }
        t -= 11400;
        if(t < 190){ int l=t/19, mm=t%19, m=mm-9;
            c_dh1[l][mm] = (abs(m)<=l) ? (float)dev_wigner_cs(l,m,0,cbh,sbh,s_ifct) : 0.f; continue; }
        t -= 190;
        if(t < 38000){ int l=t/3800, r=t%3800, z=r/190, mm=(r%190)/10, np=r%10, m=mm-9;
            c_dinv1p[l][z][mm][np] = (abs(m)<=l && np<=l) ? (float)((2*l+1)*dev_wigner_cs(l,m,np,cb40[z],sb40[z],s_ifct)) : 0.f;
            continue; }
        t -= 38000;
        if(t < 8100){ int l=t/1620, r=t%1620, z=r/81, mm=(r%81)/9, nn=r%9, m=mm-4, n=nn-4;
            c_d2[l][z][mm][nn] = (abs(m)<=l && abs(n)<=l) ? (float)(dev_wigner_cs(l,m,n,cb40[z],sb40[z],s_ifct)*s_w10[z]) : 0.f;
            continue; }
        t -= 8100;
        if(t < 405){ int l=t/81, mm=(t%81)/9, nn=t%9, m=mm-4, n=nn-4;
            c_dh2[l][mm][nn] = (abs(m)<=l && abs(n)<=l) ? (float)dev_wigner_cs(l,m,n,cbh,sbh,s_ifct) : 0.f; continue; }
        t -= 405;
        if(t < 4050){ int l=t/810, r=t%810, z=r/81, mm=(r%81)/9, nn=r%9, m=mm-4, n=nn-4;
            c_dinv2[l][z][mm][nn] = (abs(m)<=l && abs(n)<=l) ? (float)((2*l+1)*dev_wigner_cs(l,m,n,cb20[z],sb20[z],s_ifct)) : 0.f;
            continue; }
        t -= 4050;
        if(t < 1140){ int mm=t/60, p=t%60; double a = -2.0*PI_D*(double)(mm-9)*(double)p/60.0;
            c_tw60[mm][p] = make_float2((float)cos(a),(float)sin(a)); continue; }
        t -= 1140;
        if(t < 380){ int mm=t/20, j=t%20; double a = 2.0*PI_D*(double)(mm-9)*(double)j/20.0;
            float cx=(float)cos(a), cy=(float)sin(a);
            c_tw20b[mm][j]  = make_float2(cx,cy);
            c_tw20br[mm][j] = make_float2(-cy,cx);
            continue; }
        t -= 380;
        if(t < 180){ int mm=t/20, k=t%20; double a = -2.0*PI_D*(double)(mm-4)*(double)k/20.0;
            float cx=(float)cos(a), cy=(float)sin(a);
            c_tw20f[mm][k]  = make_float2(cx,cy);
            c_tw20fr[mm][k] = make_float2(-cy,cx);
            continue; }
        t -= 180;
        if(t < 90){ int mm=t/10, j=t%10; double a = 2.0*PI_D*(double)(mm-4)*(double)j/10.0;
            float cx=(float)cos(a), cy=(float)sin(a);
            c_tw10b[mm][j]  = make_float2(cx,cy);
            c_tw10br[mm][j] = make_float2(-cy,cx);
            continue; }
        t -= 90;
        { c_w5[t] = s_w5f[t]; }
    }
}

// ---------------- input DFTs: row-per-thread, radix-2 parity fold ----------------
__global__ void k_dfts(const float* __restrict__ x, const float* __restrict__ k1,
                       const float* __restrict__ k2){
    int idx = blockIdx.x*blockDim.x+threadIdx.x;
    if(idx < 1920){
        // x DFT: one thread per (b,z); fold p vs p+30 ((-1)^m); m = mmq in [0,9]
        int b = idx%32, z = idx/32;
        const float4* row4 = (const float4*)(x + (b*60 + z)*60);
        float r[60];
        #pragma unroll
        for(int i=0;i<15;i++){ float4 v=row4[i]; r[i*4]=v.x; r[i*4+1]=v.y; r[i*4+2]=v.z; r[i*4+3]=v.w; }
        float tp[30], tm[30];
        #pragma unroll
        for(int p=0;p<30;p++){ tp[p]=r[p]+r[p+30]; tm[p]=r[p]-r[p+30]; }
        #pragma unroll
        for(int mmq=0;mmq<10;mmq++){
            int mm = 9+mmq;
            const float* src = (mmq&1) ? tm : tp;
            u64 acc = 0;
            #pragma unroll
            for(int p=0;p<30;p++)
                fma2(acc, pk2(src[p],src[p]), *(const u64*)&c_tw60[mm][p]);
            float2 a = u2f(acc);
            g_xfT[mm][z][b] = a;
            if(mmq > 0) g_xfT[18-mm][z][b] = make_float2(a.x, -a.y);
        }
        return;
    }
    idx -= 1920;
    if(idx < 100){
        int o = idx;
        const float4* row4 = (const float4*)(k1 + o*60);
        float r[60];
        #pragma unroll
        for(int i=0;i<15;i++){ float4 v=row4[i]; r[i*4]=v.x; r[i*4+1]=v.y; r[i*4+2]=v.z; r[i*4+3]=v.w; }
        float tp[30], tm[30];
        #pragma unroll
        for(int p=0;p<30;p++){ tp[p]=r[p]+r[p+30]; tm[p]=r[p]-r[p+30]; }
        #pragma unroll
        for(int mmq=0;mmq<10;mmq++){
            int mm = 9+mmq;
            const float* src = (mmq&1) ? tm : tp;
            u64 acc = 0;
            #pragma unroll
            for(int p=0;p<30;p++)
                fma2(acc, pk2(src[p],src[p]), *(const u64*)&c_tw60[mm][p]);
            float2 a = u2f(acc);
            g_kfc[o][mm] = make_float2(a.x*SC1V, a.y*SC1V);
        }
        return;
    }
    idx -= 100;
    if(idx < 20000){
        // k2 DFT: one thread per (i,o); fold p vs p+10 ((-1)^m, m=mm-4 parity == mm parity)
        int o = idx%200, i = idx/200;
        const float4* row4 = (const float4*)(k2 + (i*200+o)*20);
        float r[20];
        #pragma unroll
        for(int q=0;q<5;q++){ float4 v=row4[q]; r[q*4]=v.x; r[q*4+1]=v.y; r[q*4+2]=v.z; r[q*4+3]=v.w; }
        float tp[10], tm[10];
        #pragma unroll
        for(int p=0;p<10;p++){ tp[p]=r[p]+r[p+10]; tm[p]=r[p]-r[p+10]; }
        #pragma unroll
        for(int mm=0;mm<9;mm++){
            const float* src = (mm&1) ? tm : tp;
            u64 acc = 0;
            #pragma unroll
            for(int p=0;p<10;p++)
                fma2(acc, pk2(src[p],src[p]), *(const u64*)&c_tw20f[mm][p]);
            float2 a = u2f(acc);
            g_k2f[mm][i][o] = make_float2(a.x*SC2V, a.y*SC2V);
        }
    }
}

// ---------------- FG (xhat1 in-block) + Kp (n-contiguous layout) ----------------
__global__ void k_FGmid(){
    int blk = blockIdx.x;
    int t = threadIdx.x;  // 256
    if(blk >= 640){
        int o = blk - 640;
        if(t < 200){
            int k = t/10, np = t%10;
            float2 kf = g_kfc[o][np+9];
            float2 e  = c_tw20b[np+9][k];
            g_Kp[o][k][np] = make_float2(kf.x*e.x + kf.y*e.y, kf.x*e.y - kf.y*e.x);
        }
        return;
    }
    __shared__ float2 xh1s[10][19];
    __shared__ float2 Fs[19][10];
    int b = blk/20, z2 = blk%20;
    if(t < 190){
        int l = t/19, mm = t%19, m = mm-9;
        u64 acc = 0;
        if(abs(m)<=l){
            #pragma unroll 4
            for(int z=0;z<60;z++){
                float d = c_d1[l][z][mm];
                fma2(acc, pk2(d,d), *(const u64*)&g_xfT[mm][z][b]);
            }
        }
        xh1s[l][mm] = u2f(acc);
    }
    __syncthreads();
    if(t < 190){
        int mm = t%19, np = t/19, m = mm-9;
        int l0 = max(abs(m), np);
        u64 acc = 0;
        for(int l=l0;l<10;l++){
            float c = c_dh1[l][np+9]*c_dinv1p[l][z2][mm][np];
            fma2(acc, pk2(c,c), *(const u64*)&xh1s[l][mm]);
        }
        Fs[mm][np] = u2f(acc);
    }
    __syncthreads();
    if(t < 200){
        int np = t/20, j = t%20;
        u64 acc = 0;
        #pragma unroll
        for(int mm=0;mm<19;mm++){
            float2 f = Fs[mm][np];
            fma2(acc, pk2(f.x,f.x), *(const u64*)&c_tw20b[mm][j]);
            fma2(acc, pk2(f.y,f.y), *(const u64*)&c_tw20br[mm][j]);
        }
        g_G[np][b][z2][j] = u2f(acc);
    }
}

// ---------------- S2 epilogue: parity-folded DFT stages, mirror-free tms ----------------
__global__ void __launch_bounds__(400,2) k_s2fuse(const float* __restrict__ b1){
    __shared__ __align__(16) float2 Kks[4][20][10];   // [q][k][n]
    __shared__ __align__(16) float2 hs2[4][20][10];   // [q][k][jp] = (h_jp, h_jp+10)
    __shared__ __align__(16) float4 tms4[4][5][10];   // [q][mq][kkp], mq = mm-4 (m>=0 only)
    __shared__ __align__(16) float2 s_twf[9][10];
    __shared__ __align__(16) float2 s_twfr[9][10];
    __shared__ __align__(16) float2 s_twfrn[9][10];   // negated rotated (for conj reads)
    __shared__ float  bs[100];
    int bb = blockIdx.x;
    int b = bb/40, z2 = (bb%40)>>1, ih = bb&1;
    int t = threadIdx.x;  // 400
    int r  = t%200, tq = t/200;
    int k  = r/10,  jp = r%10;
    u64 Gx[10], Gyn[10];   // packed (j0,j1) of G.x ; negated G.y
    #pragma unroll
    for(int n=0;n<10;n++){
        float2 g0 = g_G[n][b][z2][jp];
        float2 g1 = g_G[n][b][z2][jp+10];
        Gx[n]  = pk2(g0.x, g1.x);
        Gyn[n] = pk2(-g0.y, -g1.y);
    }
    if(t < 100) bs[t] = b1[t];
    if(t >= 100 && t < 190){ int q = t-100; s_twf [q/10][q%10] = c_tw20f [q/10][q%10]; }
    if(t >= 190 && t < 280){ int q = t-190; s_twfr[q/10][q%10] = c_tw20fr[q/10][q%10]; }
    if(t >= 280 && t < 370){ int q = t-280; float2 v = c_tw20fr[q/10][q%10];
                             s_twfrn[q/10][q%10] = make_float2(-v.x,-v.y); }
    __syncthreads();
    int istart = ih*52, iend = istart ? 100 : 52;
    for(int i0=istart;i0<iend;i0+=4){
        // Kks fill: straight float4 copy
        ((float4*)&Kks[0][0][0])[t] = ((const float4*)&g_Kp[i0][0][0])[t];
        __syncthreads();
        // h-stage: 2q x 2j per thread; the (jp, jp+10) pair is written as one float2
        #pragma unroll
        for(int qq=0;qq<2;qq++){
            int q = tq*2+qq;
            const float4* krow = (const float4*)&Kks[q][k][0];
            float4 K01=krow[0], K23=krow[1], K45=krow[2], K67=krow[3], K89=krow[4];
            u64 a = 0, p = 0;
            fma2(a, pk2(K01.x,K01.x), Gx[0]); fma2(a, pk2(K01.y,K01.y), Gyn[0]);
            fma2(p, pk2(K01.z,K01.z), Gx[1]); fma2(p, pk2(K01.w,K01.w), Gyn[1]);
            fma2(p, pk2(K23.x,K23.x), Gx[2]); fma2(p, pk2(K23.y,K23.y), Gyn[2]);
            fma2(p, pk2(K23.z,K23.z), Gx[3]); fma2(p, pk2(K23.w,K23.w), Gyn[3]);
            fma2(p, pk2(K45.x,K45.x), Gx[4]); fma2(p, pk2(K45.y,K45.y), Gyn[4]);
            fma2(p, pk2(K45.z,K45.z), Gx[5]); fma2(p, pk2(K45.w,K45.w), Gyn[5]);
            fma2(p, pk2(K67.x,K67.x), Gx[6]); fma2(p, pk2(K67.y,K67.y), Gyn[6]);
            fma2(p, pk2(K67.z,K67.z), Gx[7]); fma2(p, pk2(K67.w,K67.w), Gyn[7]);
            fma2(p, pk2(K89.x,K89.x), Gx[8]); fma2(p, pk2(K89.y,K89.y), Gyn[8]);
            fma2(p, pk2(K89.z,K89.z), Gx[9]); fma2(p, pk2(K89.w,K89.w), Gyn[9]);
            float2 af = u2f(a), pf = u2f(p);
            float bias = bs[i0+q];
            hs2[q][k][jp] = make_float2(fmaxf(bias + af.x + 2.f*pf.x, 0.f),
                                        fmaxf(bias + af.y + 2.f*pf.y, 0.f));
        }
        __syncthreads();
        // st1: j-parity fold; mq fast / kk slow; only m>=0 rows stored (no mirror)
        {
            int q = t/100, rr = t%100, mq = rr%5, kk = rr/5, mm = 4+mq;
            float sgn = (mq&1) ? -1.f : 1.f;
            const float4* hrow  = (const float4*)&hs2[q][kk][0];   // 5 float4 = 10 jp pairs
            const float4* twrow = (const float4*)&s_twf[mm][0];    // 5 float4 = 10 jp
            u64 acc = 0;
            #pragma unroll
            for(int c=0;c<5;c++){
                float4 hv = hrow[c];
                float4 e  = twrow[c];
                float t0 = fmaf(sgn, hv.y, hv.x);
                float t1 = fmaf(sgn, hv.w, hv.z);
                fma2(acc, pk2(t0,t0), pk2(e.x,e.y));
                fma2(acc, pk2(t1,t1), pk2(e.z,e.w));
            }
            float2 a = u2f(acc);
            int kkp = kk%10, half = kk/10;
            ((float2*)&tms4[q][mq][kkp])[half] = a;
        }
        __syncthreads();
        // st2: k-parity fold; read source row 4-mm, conj via negated twiddle table
        if(t < 164){
            int q = t/41, mn = t%41, mm = mn/9, nn = mn%9;
            float sgn = (nn&1) ? -1.f : 1.f;
            u64 sg2 = pk2(sgn,sgn);
            const float4* trow = (const float4*)&tms4[q][4-mm][0];  // source row (m>=0 set)
            const float4* twf  = (const float4*)&s_twf[nn][0];
            const float4* twr  = (mm<4) ? (const float4*)&s_twfrn[nn][0]
                                        : (const float4*)&s_twfr[nn][0];
            u64 acc = 0;
            #pragma unroll
            for(int c=0;c<5;c++){
                float4 e  = twf[c];
                float4 er = twr[c];
                float4 v0 = trow[2*c];
                float4 v1 = trow[2*c+1];
                u64 t0 = pk2(v0.x,v0.y); fma2(t0, sg2, pk2(v0.z,v0.w));
                u64 t1 = pk2(v1.x,v1.y); fma2(t1, sg2, pk2(v1.z,v1.w));
                float2 f0 = u2f(t0), f1 = u2f(t1);
                fma2(acc, pk2(f0.x,f0.x), pk2(e.x,e.y));
                fma2(acc, pk2(f0.y,f0.y), pk2(er.x,er.y));
                fma2(acc, pk2(f1.x,f1.x), pk2(e.z,e.w));
                fma2(acc, pk2(f1.y,f1.y), pk2(er.z,er.w));
            }
            float2 a = u2f(acc);
            g_xg[b][i0+q][z2][mn] = a;
            if(mn < 40) g_xg[b][i0+q][z2][80-mn] = make_float2(a.x, -a.y);
        }
    }
}

// ---------------- xhat2 + T2 per (b,i), half-set ----------------
__global__ void k_xh2T2(){
    __shared__ float2 xgs[20][45];
    __shared__ float2 xh[5][5][9];
    int b = blockIdx.x/100, i = blockIdx.x%100;
    int t = threadIdx.x;  // 256
    for(int idx=t; idx<900; idx+=256){
        int z = idx/45, mn = idx%45;
        xgs[z][mn] = g_xg[b][i][z][mn];
    }
    __syncthreads();
    if(t < 225){
        int l = t/45, rr = t%45, mm = rr/9, kk = rr%9;
        int m = mm-4, kq = kk-4;
        u64 acc = 0;
        if(abs(m)<=l && abs(kq)<=l){
            #pragma unroll 4
            for(int z=0;z<20;z++){
                float d = c_d2[l][z][mm][kk];
                fma2(acc, pk2(d,d), *(const u64*)&xgs[z][mm*9+kk]);
            }
        }
        xh[l][mm][kk] = u2f(acc);
    }
    __syncthreads();
    if(t < 205){
        int l = t/41, mn = t%41, mm = mn/9, nn = mn%9;
        u64 acc = 0;
        #pragma unroll
        for(int kk=0;kk<9;kk++){
            float d = c_dh2[l][nn][kk];
            fma2(acc, pk2(d,d), *(const u64*)&xh[l][mm][kk]);
        }
        g_T2[l][mn][b][i] = u2f(acc);
    }
}

// ---------------- z2: half-set GEMM, b-split x2, packed ----------------
__global__ void k_z2(){
    __shared__ float2 Ts[16][100];
    int blk = blockIdx.x;
    int bh = blk/205, lh = blk%205;
    int l = lh/41, h = lh%41;
    int mm = h/9, nn = h%9;
    int m = mm-4, n = nn-4;
    int t = threadIdx.x;  // 256
    if(l < max(abs(m),abs(n))) return;
    const float2* src = &g_T2[l][h][bh*16][0];
    for(int idx=t; idx<1600; idx+=256) (&Ts[0][0])[idx] = src[idx];
    __syncthreads();
    if(t < 200){
        int bq = t/100, op = t%100;
        float sg = ((mm+nn)&1) ? -1.f : 1.f;
        int idx0 = l*81 + h, idx1 = l*81 + (80-h);
        int bb0 = bq*8;
        u64 a0[8], a1[8];
        #pragma unroll
        for(int rr=0;rr<8;rr++){ a0[rr]=0; a1[rr]=0; }
        for(int i=0;i<100;i++){
            float2 kf0 = g_k2f[nn][i][op];
            float2 kf1 = g_k2f[nn][i][op+100];
            u64 ka0 = pk2(kf0.x,-kf0.y), kb0 = pk2(kf0.y,kf0.x);
            u64 ka1 = pk2(kf1.x,-kf1.y), kb1 = pk2(kf1.y,kf1.x);
            #pragma unroll
            for(int rr=0;rr<8;rr++){
                float2 Tv = Ts[bb0+rr][i];
                u64 tx = pk2(Tv.x,Tv.x), ty = pk2(Tv.y,Tv.y);
                fma2(a0[rr], tx, ka0); fma2(a0[rr], ty, kb0);
                fma2(a1[rr], tx, ka1); fma2(a1[rr], ty, kb1);
            }
        }
        #pragma unroll
        for(int rr=0;rr<8;rr++){
            int bb = bh*16 + bb0 + rr;
            float2 v0 = u2f(a0[rr]), v1 = u2f(a1[rr]);
            g_z2t[bb][op    ][idx0] = v0;
            g_z2t[bb][op+100][idx0] = v1;
            if(h < 40){
                g_z2t[bb][op    ][idx1] = make_float2(sg*v0.x, -sg*v0.y);
                g_z2t[bb][op+100][idx1] = make_float2(sg*v1.x, -sg*v1.y);
            }
        }
    }
}

// ---------------- out2: packed stages + fused final via atomics ----------------
__global__ void k_out2(const float* __restrict__ b2, const float* __restrict__ W,
                       float* __restrict__ out){
    __shared__ float2 zs[405];
    __shared__ float2 g2a[10][81];
    __shared__ float2 tma[10][5][10];
    __shared__ float  wsum[8];
    int b = blockIdx.x/200, o = blockIdx.x%200;
    int t = threadIdx.x;  // 256
    for(int idx=t; idx<405; idx+=256){
        int l = idx/81, mn = idx%81, m = mn/9-4, n = mn%9-4;
        zs[idx] = (l >= max(abs(m),abs(n))) ? g_z2t[b][o][idx] : make_float2(0.f,0.f);
    }
    float b2v = b2[o];
    __syncthreads();
    for(int idx=t; idx<410; idx+=256){
        int z3 = idx/41, mn = idx%41, mm = mn/9, nn = mn%9;
        int m = mm-4, n = nn-4;
        int l0 = max(abs(m),abs(n));
        u64 acc = 0;
        for(int l=l0;l<5;l++){
            float d = c_dinv2[l][z3][mm][nn];
            fma2(acc, pk2(d,d), *(const u64*)&zs[l*81+mn]);
        }
        float2 a = u2f(acc);
        g2a[z3][mn] = a;
        g2a[z3][80-mn] = make_float2(a.x, -a.y);
    }
    __syncthreads();
    for(int idx=t; idx<500; idx+=256){
        int z3 = idx/50, rr = idx%50, mq = rr/10, k = rr%10;
        int mm = 4+mq;
        u64 acc = 0;
        #pragma unroll
        for(int nn=0;nn<9;nn++){
            float2 v = g2a[z3][mm*9+nn];
            fma2(acc, pk2(v.x,v.x), *(const u64*)&c_tw10b[nn][k]);
            fma2(acc, pk2(v.y,v.y), *(const u64*)&c_tw10br[nn][k]);
        }
        tma[z3][mq][k] = u2f(acc);
    }
    __syncthreads();
    float psum = 0.f;
    for(int idx=t; idx<1000; idx+=256){
        int z3 = idx/100, rr = idx%100, j = rr/10, k = rr%10;
        float v = tma[z3][0][k].x;
        #pragma unroll
        for(int mq=1;mq<5;mq++){
            float2 a = tma[z3][mq][k]; float2 e = c_tw10b[4+mq][j];
            v += 2.f*(a.x*e.x - a.y*e.y);
        }
        v = fmaxf(v + b2v, 0.f);
        psum += v * c_w5[z3];
    }
    #pragma unroll
    for(int off=16; off; off>>=1) psum += __shfl_xor_sync(0xFFFFFFFFu, psum, off);
    if((t&31) == 0) wsum[t>>5] = psum;
    __syncthreads();
    if(t < 10){
        float s = 0.f;
        #pragma unroll
        for(int w=0;w<8;w++) s += wsum[w];
        atomicAdd(&out[b*10+t], s*W[t*200+o]);
    }
}

extern "C" void kernel_launch(void* const* d_in, const int* in_sizes, int n_in,
                              void* d_out, int out_size){
    const float* x  = (const float*)d_in[0];
    const float* k1 = (const float*)d_in[1];
    const float* b1 = (const float*)d_in[2];
    const float* k2 = (const float*)d_in[3];
    const float* b2 = (const float*)d_in[4];
    const float* W  = (const float*)d_in[5];
    const float* bl = (const float*)d_in[6];
    float* out = (float*)d_out;

    k_init  <<<128,256>>>(bl,out);
    k_dfts  <<<(1920+100+20000+255)/256,256>>>(x,k1,k2);
    k_FGmid <<<740,256>>>();
    k_s2fuse<<<1280,400>>>(b1);
    k_xh2T2 <<<3200,256>>>();
    k_z2    <<<410,256>>>();
    k_out2  <<<6400,256>>>(b2,W,out);
}

// round 15
// speedup vs baseline: 1.0190x; 1.0190x over previous
#include <cuda_runtime.h>
#include <math.h>

#define PI_D 3.14159265358979323846
#define SC1V 0.03872983346207417f   /* 1/sqrt(2000/3) */
#define SC2V 0.06324555320336759f   /* 1/sqrt(250)    */

typedef unsigned long long u64;

// packed f32x2 helpers
__device__ __forceinline__ float2 u2f(u64 v){ float2 r; asm("mov.b64 {%0,%1}, %2;":"=f"(r.x),"=f"(r.y):"l"(v)); return r; }
__device__ __forceinline__ u64 pk2(float a, float b){ u64 r; asm("mov.b64 %0, {%1,%2};":"=l"(r):"f"(a),"f"(b)); return r; }
__device__ __forceinline__ void fma2(u64 &acc, u64 a, u64 b){
    asm("fma.rn.f32x2 %0, %1, %2, %3;" : "=l"(acc) : "l"(a), "l"(b), "l"(acc));
}

// ---------------- constant tables (device-computed) ----------------
__device__ float  c_d1[10][60][19];
__device__ float  c_dh1[10][19];
__device__ float  c_dinv1p[10][20][19][10];
__device__ float  c_d2[5][20][9][9];
__device__ float  c_dh2[5][9][9];
__device__ float  c_dinv2[5][10][9][9];
__device__ float  c_w5[10];
__device__ float2 c_tw60[19][60];                 // e^{-2pi i m p/60}
__device__ float2 c_tw20b[19][20];                // e^{+2pi i m j/20}
__device__ float2 c_tw20br[19][20];               // rotated (-y,x)
__device__ __align__(16) float2 c_tw20f[9][20];   // e^{-2pi i m k/20}
__device__ __align__(16) float2 c_tw20fr[9][20];  // rotated
__device__ float2 c_tw10b[9][10];                 // e^{+2pi i m j/10}
__device__ float2 c_tw10br[9][10];                // rotated

__constant__ double c_fct[20] = {1.,1.,2.,6.,24.,120.,720.,5040.,40320.,362880.,
    3628800.,39916800.,479001600.,6227020800.,87178291200.,1307674368000.,
    20922789888000.,355687428096000.,6402373705728000.,121645100408832000.};

// ---------------- scratch ----------------
__device__ float2 g_xfT[19][60][32];
__device__ float2 g_kfc[100][19];
__device__ __align__(16) float2 g_Kp[100][20][10];   // [i][k][n]  (n contiguous)
__device__ float2 g_G[10][32][20][20];
__device__ float2 g_xg[32][100][20][81];
__device__ float2 g_k2f[9][100][200];
__device__ float2 g_T2[5][41][32][100];
__device__ float2 g_z2t[32][200][405];

// ---------------- Wigner-d from precomputed half-angle cos/sin ----------------
__device__ double dev_wigner_cs(int l, int m, int n, double cb, double sb, const double* ifct){
    double pref = sqrt(c_fct[l+m]*c_fct[l-m]*c_fct[l+n]*c_fct[l-n]);
    int s0 = (n-m > 0) ? (n-m) : 0;
    int s1 = (l+n < l-m) ? (l+n) : (l-m);
    if(s1 < s0) return 0.0;
    int e0 = 2*l+n-m-2*s0, f0 = m-n+2*s0;
    double cbe = 1.0; for(int i=0;i<e0;i++) cbe *= cb;
    double sbf = 1.0; for(int i=0;i<f0;i++) sbf *= sb;
    double r  = (sb*sb)/(cb*cb);
    double pw = cbe*sbf;
    double acc = 0.0;
    for(int s=s0;s<=s1;s++){
        double deni = ifct[l+n-s]*ifct[s]*ifct[m-n+s]*ifct[l-m-s];
        double sg   = ((m-n+s)&1) ? -1.0 : 1.0;
        acc += sg*pw*deni;
        pw *= r;
    }
    return pref*acc;
}

__device__ double dev_qw(int b, int j){
    double beta = PI_D*(2*j+1)/(4.0*b);
    double s=0.0;
    for(int k=1;k<2*b;k+=2) s += sin(k*beta)/(double)k;
    return 2.0/b*sin(beta)*s;
}

// ---------------- init: output reset + per-block smem weights + all tables ----------------
__global__ void k_init(const float* __restrict__ bl, float* __restrict__ out){
    {
        int gi = blockIdx.x*blockDim.x + threadIdx.x;
        if(gi < 320) out[gi] = bl[gi%10];
    }
    __shared__ double s_w30[60], s_w10[20];
    __shared__ float  s_w5f[10];
    __shared__ double cb120[60], sb120[60], cb40[20], sb40[20], cb20[10], sb20[10];
    __shared__ double s_ifct[20];
    int tt = threadIdx.x;
    if(tt < 60){ s_w30[tt]=dev_qw(30,tt); double a=PI_D*(2*tt+1)/240.0; cb120[tt]=cos(a); sb120[tt]=sin(a); }
    else if(tt < 80){ int z=tt-60; s_w10[z]=dev_qw(10,z); double a=PI_D*(2*z+1)/80.0; cb40[z]=cos(a); sb40[z]=sin(a); }
    else if(tt < 90){ int z=tt-80; s_w5f[z]=(float)dev_qw(5,z); double a=PI_D*(2*z+1)/40.0; cb20[z]=cos(a); sb20[z]=sin(a); }
    else if(tt < 110){ s_ifct[tt-90] = 1.0/c_fct[tt-90]; }
    __syncthreads();
    const double cbh = 0.70710678118654752, sbh = 0.70710678118654752;
    const int total = 11400+190+38000+8100+405+4050+1140+380+180+90+10;
    for(int idx = blockIdx.x*blockDim.x+threadIdx.x; idx<total; idx += gridDim.x*blockDim.x){
        int t = idx;
        if(t < 11400){ int l=t/1140, r=t%1140, z=r/19, mm=r%19, m=mm-9;
            c_d1[l][z][mm] = (abs(m)<=l) ? (float)(dev_wigner_cs(l,m,0,cb120[z],sb120[z],s_ifct)*s_w30[z]) : 0.f;
            continue; }
        t -= 11400;
        if(t < 190){ int l=t/19, mm=t%19, m=mm-9;
            c_dh1[l][mm] = (abs(m)<=l) ? (float)dev_wigner_cs(l,m,0,cbh,sbh,s_ifct) : 0.f; continue; }
        t -= 190;
        if(t < 38000){ int l=t/3800, r=t%3800, z=r/190, mm=(r%190)/10, np=r%10, m=mm-9;
            c_dinv1p[l][z][mm][np] = (abs(m)<=l && np<=l) ? (float)((2*l+1)*dev_wigner_cs(l,m,np,cb40[z],sb40[z],s_ifct)) : 0.f;
            continue; }
        t -= 38000;
        if(t < 8100){ int l=t/1620, r=t%1620, z=r/81, mm=(r%81)/9, nn=r%9, m=mm-4, n=nn-4;
            c_d2[l][z][mm][nn] = (abs(m)<=l && abs(n)<=l) ? (float)(dev_wigner_cs(l,m,n,cb40[z],sb40[z],s_ifct)*s_w10[z]) : 0.f;
            continue; }
        t -= 8100;
        if(t < 405){ int l=t/81, mm=(t%81)/9, nn=t%9, m=mm-4, n=nn-4;
            c_dh2[l][mm][nn] = (abs(m)<=l && abs(n)<=l) ? (float)dev_wigner_cs(l,m,n,cbh,sbh,s_ifct) : 0.f; continue; }
        t -= 405;
        if(t < 4050){ int l=t/810, r=t%810, z=r/81, mm=(r%81)/9, nn=r%9, m=mm-4, n=nn-4;
            c_dinv2[l][z][mm][nn] = (abs(m)<=l && abs(n)<=l) ? (float)((2*l+1)*dev_wigner_cs(l,m,n,cb20[z],sb20[z],s_ifct)) : 0.f;
            continue; }
        t -= 4050;
        if(t < 1140){ int mm=t/60, p=t%60; double a = -2.0*PI_D*(double)(mm-9)*(double)p/60.0;
            c_tw60[mm][p] = make_float2((float)cos(a),(float)sin(a)); continue; }
        t -= 1140;
        if(t < 380){ int mm=t/20, j=t%20; double a = 2.0*PI_D*(double)(mm-9)*(double)j/20.0;
            float cx=(float)cos(a), cy=(float)sin(a);
            c_tw20b[mm][j]  = make_float2(cx,cy);
            c_tw20br[mm][j] = make_float2(-cy,cx);
            continue; }
        t -= 380;
        if(t < 180){ int mm=t/20, k=t%20; double a = -2.0*PI_D*(double)(mm-4)*(double)k/20.0;
            float cx=(float)cos(a), cy=(float)sin(a);
            c_tw20f[mm][k]  = make_float2(cx,cy);
            c_tw20fr[mm][k] = make_float2(-cy,cx);
            continue; }
        t -= 180;
        if(t < 90){ int mm=t/10, j=t%10; double a = 2.0*PI_D*(double)(mm-4)*(double)j/10.0;
            float cx=(float)cos(a), cy=(float)sin(a);
            c_tw10b[mm][j]  = make_float2(cx,cy);
            c_tw10br[mm][j] = make_float2(-cy,cx);
            continue; }
        t -= 90;
        { c_w5[t] = s_w5f[t]; }
    }
}

// ---------------- input DFTs: row-per-thread, radix-2 parity fold ----------------
__global__ void k_dfts(const float* __restrict__ x, const float* __restrict__ k1,
                       const float* __restrict__ k2){
    int idx = blockIdx.x*blockDim.x+threadIdx.x;
    if(idx < 1920){
        int b = idx%32, z = idx/32;
        const float4* row4 = (const float4*)(x + (b*60 + z)*60);
        float r[60];
        #pragma unroll
        for(int i=0;i<15;i++){ float4 v=row4[i]; r[i*4]=v.x; r[i*4+1]=v.y; r[i*4+2]=v.z; r[i*4+3]=v.w; }
        float tp[30], tm[30];
        #pragma unroll
        for(int p=0;p<30;p++){ tp[p]=r[p]+r[p+30]; tm[p]=r[p]-r[p+30]; }
        #pragma unroll
        for(int mmq=0;mmq<10;mmq++){
            int mm = 9+mmq;
            const float* src = (mmq&1) ? tm : tp;
            u64 acc = 0;
            #pragma unroll
            for(int p=0;p<30;p++)
                fma2(acc, pk2(src[p],src[p]), *(const u64*)&c_tw60[mm][p]);
            float2 a = u2f(acc);
            g_xfT[mm][z][b] = a;
            if(mmq > 0) g_xfT[18-mm][z][b] = make_float2(a.x, -a.y);
        }
        return;
    }
    idx -= 1920;
    if(idx < 100){
        int o = idx;
        const float4* row4 = (const float4*)(k1 + o*60);
        float r[60];
        #pragma unroll
        for(int i=0;i<15;i++){ float4 v=row4[i]; r[i*4]=v.x; r[i*4+1]=v.y; r[i*4+2]=v.z; r[i*4+3]=v.w; }
        float tp[30], tm[30];
        #pragma unroll
        for(int p=0;p<30;p++){ tp[p]=r[p]+r[p+30]; tm[p]=r[p]-r[p+30]; }
        #pragma unroll
        for(int mmq=0;mmq<10;mmq++){
            int mm = 9+mmq;
            const float* src = (mmq&1) ? tm : tp;
            u64 acc = 0;
            #pragma unroll
            for(int p=0;p<30;p++)
                fma2(acc, pk2(src[p],src[p]), *(const u64*)&c_tw60[mm][p]);
            float2 a = u2f(acc);
            g_kfc[o][mm] = make_float2(a.x*SC1V, a.y*SC1V);
        }
        return;
    }
    idx -= 100;
    if(idx < 20000){
        int o = idx%200, i = idx/200;
        const float4* row4 = (const float4*)(k2 + (i*200+o)*20);
        float r[20];
        #pragma unroll
        for(int q=0;q<5;q++){ float4 v=row4[q]; r[q*4]=v.x; r[q*4+1]=v.y; r[q*4+2]=v.z; r[q*4+3]=v.w; }
        float tp[10], tm[10];
        #pragma unroll
        for(int p=0;p<10;p++){ tp[p]=r[p]+r[p+10]; tm[p]=r[p]-r[p+10]; }
        #pragma unroll
        for(int mm=0;mm<9;mm++){
            const float* src = (mm&1) ? tm : tp;
            u64 acc = 0;
            #pragma unroll
            for(int p=0;p<10;p++)
                fma2(acc, pk2(src[p],src[p]), *(const u64*)&c_tw20f[mm][p]);
            float2 a = u2f(acc);
            g_k2f[mm][i][o] = make_float2(a.x*SC2V, a.y*SC2V);
        }
    }
}

// ---------------- FG (xhat1 in-block) + Kp (n-contiguous layout) ----------------
__global__ void k_FGmid(){
    int blk = blockIdx.x;
    int t = threadIdx.x;  // 256
    if(blk >= 640){
        int o = blk - 640;
        if(t < 200){
            int k = t/10, np = t%10;
            float2 kf = g_kfc[o][np+9];
            float2 e  = c_tw20b[np+9][k];
            g_Kp[o][k][np] = make_float2(kf.x*e.x + kf.y*e.y, kf.x*e.y - kf.y*e.x);
        }
        return;
    }
    __shared__ float2 xh1s[10][19];
    __shared__ float2 Fs[19][10];
    int b = blk/20, z2 = blk%20;
    if(t < 190){
        int l = t/19, mm = t%19, m = mm-9;
        u64 acc = 0;
        if(abs(m)<=l){
            #pragma unroll 4
            for(int z=0;z<60;z++){
                float d = c_d1[l][z][mm];
                fma2(acc, pk2(d,d), *(const u64*)&g_xfT[mm][z][b]);
            }
        }
        xh1s[l][mm] = u2f(acc);
    }
    __syncthreads();
    if(t < 190){
        int mm = t%19, np = t/19, m = mm-9;
        int l0 = max(abs(m), np);
        u64 acc = 0;
        for(int l=l0;l<10;l++){
            float c = c_dh1[l][np+9]*c_dinv1p[l][z2][mm][np];
            fma2(acc, pk2(c,c), *(const u64*)&xh1s[l][mm]);
        }
        Fs[mm][np] = u2f(acc);
    }
    __syncthreads();
    if(t < 200){
        int np = t/20, j = t%20;
        u64 acc = 0;
        #pragma unroll
        for(int mm=0;mm<19;mm++){
            float2 f = Fs[mm][np];
            fma2(acc, pk2(f.x,f.x), *(const u64*)&c_tw20b[mm][j]);
            fma2(acc, pk2(f.y,f.y), *(const u64*)&c_tw20br[mm][j]);
        }
        g_G[np][b][z2][j] = u2f(acc);
    }
}

// ---------------- S2 epilogue: parity-folded stages, prefetched Kks, trimmed stores ----------------
__global__ void __launch_bounds__(400,2) k_s2fuse(const float* __restrict__ b1){
    __shared__ __align__(16) float2 Kks[4][20][10];   // [q][k][n]
    __shared__ __align__(16) float2 hs2[4][20][10];   // [q][k][jp] = (h_jp, h_jp+10)
    __shared__ __align__(16) float4 tms4[4][5][10];   // [q][mq][kkp], mq = mm-4 (m>=0 only)
    __shared__ __align__(16) float2 s_twf[9][10];
    __shared__ __align__(16) float2 s_twfr[9][10];
    __shared__ __align__(16) float2 s_twfrn[9][10];   // negated rotated (for conj reads)
    __shared__ float  bs[100];
    int bb = blockIdx.x;
    int b = bb/40, z2 = (bb%40)>>1, ih = bb&1;
    int t = threadIdx.x;  // 400
    int r  = t%200, tq = t/200;
    int k  = r/10,  jp = r%10;
    u64 Gx[10], Gyn[10];   // packed (j0,j1) of G.x ; negated G.y
    #pragma unroll
    for(int n=0;n<10;n++){
        float2 g0 = g_G[n][b][z2][jp];
        float2 g1 = g_G[n][b][z2][jp+10];
        Gx[n]  = pk2(g0.x, g1.x);
        Gyn[n] = pk2(-g0.y, -g1.y);
    }
    if(t < 100) bs[t] = b1[t];
    if(t >= 100 && t < 190){ int q = t-100; s_twf [q/10][q%10] = c_tw20f [q/10][q%10]; }
    if(t >= 190 && t < 280){ int q = t-190; s_twfr[q/10][q%10] = c_tw20fr[q/10][q%10]; }
    if(t >= 280 && t < 370){ int q = t-280; float2 v = c_tw20fr[q/10][q%10];
                             s_twfrn[q/10][q%10] = make_float2(-v.x,-v.y); }
    int istart = ih*52, iend = istart ? 100 : 52;
    // prefetch first Kks tile into registers
    float4 pre = ((const float4*)&g_Kp[istart][0][0])[t];
    __syncthreads();
    for(int i0=istart;i0<iend;i0+=4){
        // Kks fill from prefetch register
        ((float4*)&Kks[0][0][0])[t] = pre;
        __syncthreads();
        // issue next prefetch immediately (consumed 3 phases later)
        if(i0+4 < iend) pre = ((const float4*)&g_Kp[i0+4][0][0])[t];
        // h-stage: 2q x 2j per thread; the (jp, jp+10) pair is written as one float2
        #pragma unroll
        for(int qq=0;qq<2;qq++){
            int q = tq*2+qq;
            const float4* krow = (const float4*)&Kks[q][k][0];
            float4 K01=krow[0], K23=krow[1], K45=krow[2], K67=krow[3], K89=krow[4];
            u64 a = 0, p = 0;
            fma2(a, pk2(K01.x,K01.x), Gx[0]); fma2(a, pk2(K01.y,K01.y), Gyn[0]);
            fma2(p, pk2(K01.z,K01.z), Gx[1]); fma2(p, pk2(K01.w,K01.w), Gyn[1]);
            fma2(p, pk2(K23.x,K23.x), Gx[2]); fma2(p, pk2(K23.y,K23.y), Gyn[2]);
            fma2(p, pk2(K23.z,K23.z), Gx[3]); fma2(p, pk2(K23.w,K23.w), Gyn[3]);
            fma2(p, pk2(K45.x,K45.x), Gx[4]); fma2(p, pk2(K45.y,K45.y), Gyn[4]);
            fma2(p, pk2(K45.z,K45.z), Gx[5]); fma2(p, pk2(K45.w,K45.w), Gyn[5]);
            fma2(p, pk2(K67.x,K67.x), Gx[6]); fma2(p, pk2(K67.y,K67.y), Gyn[6]);
            fma2(p, pk2(K67.z,K67.z), Gx[7]); fma2(p, pk2(K67.w,K67.w), Gyn[7]);
            fma2(p, pk2(K89.x,K89.x), Gx[8]); fma2(p, pk2(K89.y,K89.y), Gyn[8]);
            fma2(p, pk2(K89.z,K89.z), Gx[9]); fma2(p, pk2(K89.w,K89.w), Gyn[9]);
            float2 af = u2f(a), pf = u2f(p);
            float bias = bs[i0+q];
            hs2[q][k][jp] = make_float2(fmaxf(bias + af.x + 2.f*pf.x, 0.f),
                                        fmaxf(bias + af.y + 2.f*pf.y, 0.f));
        }
        __syncthreads();
        // st1: j-parity fold; mq fast / kk slow; only m>=0 rows stored
        {
            int q = t/100, rr = t%100, mq = rr%5, kk = rr/5, mm = 4+mq;
            float sgn = (mq&1) ? -1.f : 1.f;
            const float4* hrow  = (const float4*)&hs2[q][kk][0];
            const float4* twrow = (const float4*)&s_twf[mm][0];
            u64 acc = 0;
            #pragma unroll
            for(int c=0;c<5;c++){
                float4 hv = hrow[c];
                float4 e  = twrow[c];
                float t0 = fmaf(sgn, hv.y, hv.x);
                float t1 = fmaf(sgn, hv.w, hv.z);
                fma2(acc, pk2(t0,t0), pk2(e.x,e.y));
                fma2(acc, pk2(t1,t1), pk2(e.z,e.w));
            }
            float2 a = u2f(acc);
            int kkp = kk%10, half = kk/10;
            ((float2*)&tms4[q][mq][kkp])[half] = a;
        }
        __syncthreads();
        // st2: k-parity fold; conj of m<0 via negated twiddle; write only consumed mn
        if(t < 164){
            int q = t/41, mn = t%41, mm = mn/9, nn = mn%9;
            float sgn = (nn&1) ? -1.f : 1.f;
            u64 sg2 = pk2(sgn,sgn);
            const float4* trow = (const float4*)&tms4[q][4-mm][0];
            const float4* twf  = (const float4*)&s_twf[nn][0];
            const float4* twr  = (mm<4) ? (const float4*)&s_twfrn[nn][0]
                                        : (const float4*)&s_twfr[nn][0];
            u64 acc = 0;
            #pragma unroll
            for(int c=0;c<5;c++){
                float4 e  = twf[c];
                float4 er = twr[c];
                float4 v0 = trow[2*c];
                float4 v1 = trow[2*c+1];
                u64 t0 = pk2(v0.x,v0.y); fma2(t0, sg2, pk2(v0.z,v0.w));
                u64 t1 = pk2(v1.x,v1.y); fma2(t1, sg2, pk2(v1.z,v1.w));
                float2 f0 = u2f(t0), f1 = u2f(t1);
                fma2(acc, pk2(f0.x,f0.x), pk2(e.x,e.y));
                fma2(acc, pk2(f0.y,f0.y), pk2(er.x,er.y));
                fma2(acc, pk2(f1.x,f1.x), pk2(e.z,e.w));
                fma2(acc, pk2(f1.y,f1.y), pk2(er.z,er.w));
            }
            float2 a = u2f(acc);
            g_xg[b][i0+q][z2][mn] = a;
            // mirror needed only for indices 41..44 (xh2T2 reads mn<45)
            if(mn > 35 && mn < 40) g_xg[b][i0+q][z2][80-mn] = make_float2(a.x, -a.y);
        }
    }
}

// ---------------- xhat2 + T2 per (b,i), half-set ----------------
__global__ void k_xh2T2(){
    __shared__ float2 xgs[20][45];
    __shared__ float2 xh[5][5][9];
    int b = blockIdx.x/100, i = blockIdx.x%100;
    int t = threadIdx.x;  // 256
    for(int idx=t; idx<900; idx+=256){
        int z = idx/45, mn = idx%45;
        xgs[z][mn] = g_xg[b][i][z][mn];
    }
    __syncthreads();
    if(t < 225){
        int l = t/45, rr = t%45, mm = rr/9, kk = rr%9;
        int m = mm-4, kq = kk-4;
        u64 acc = 0;
        if(abs(m)<=l && abs(kq)<=l){
            #pragma unroll 4
            for(int z=0;z<20;z++){
                float d = c_d2[l][z][mm][kk];
                fma2(acc, pk2(d,d), *(const u64*)&xgs[z][mm*9+kk]);
            }
        }
        xh[l][mm][kk] = u2f(acc);
    }
    __syncthreads();
    if(t < 205){
        int l = t/41, mn = t%41, mm = mn/9, nn = mn%9;
        u64 acc = 0;
        #pragma unroll
        for(int kk=0;kk<9;kk++){
            float d = c_dh2[l][nn][kk];
            fma2(acc, pk2(d,d), *(const u64*)&xh[l][mm][kk]);
        }
        g_T2[l][mn][b][i] = u2f(acc);
    }
}

// ---------------- z2: half-set GEMM, b-split x2, packed ----------------
__global__ void k_z2(){
    __shared__ float2 Ts[16][100];
    int blk = blockIdx.x;
    int bh = blk/205, lh = blk%205;
    int l = lh/41, h = lh%41;
    int mm = h/9, nn = h%9;
    int m = mm-4, n = nn-4;
    int t = threadIdx.x;  // 256
    if(l < max(abs(m),abs(n))) return;
    const float2* src = &g_T2[l][h][bh*16][0];
    for(int idx=t; idx<1600; idx+=256) (&Ts[0][0])[idx] = src[idx];
    __syncthreads();
    if(t < 200){
        int bq = t/100, op = t%100;
        float sg = ((mm+nn)&1) ? -1.f : 1.f;
        int idx0 = l*81 + h, idx1 = l*81 + (80-h);
        int bb0 = bq*8;
        u64 a0[8], a1[8];
        #pragma unroll
        for(int rr=0;rr<8;rr++){ a0[rr]=0; a1[rr]=0; }
        for(int i=0;i<100;i++){
            float2 kf0 = g_k2f[nn][i][op];
            float2 kf1 = g_k2f[nn][i][op+100];
            u64 ka0 = pk2(kf0.x,-kf0.y), kb0 = pk2(kf0.y,kf0.x);
            u64 ka1 = pk2(kf1.x,-kf1.y), kb1 = pk2(kf1.y,kf1.x);
            #pragma unroll
            for(int rr=0;rr<8;rr++){
                float2 Tv = Ts[bb0+rr][i];
                u64 tx = pk2(Tv.x,Tv.x), ty = pk2(Tv.y,Tv.y);
                fma2(a0[rr], tx, ka0); fma2(a0[rr], ty, kb0);
                fma2(a1[rr], tx, ka1); fma2(a1[rr], ty, kb1);
            }
        }
        #pragma unroll
        for(int rr=0;rr<8;rr++){
            int bb = bh*16 + bb0 + rr;
            float2 v0 = u2f(a0[rr]), v1 = u2f(a1[rr]);
            g_z2t[bb][op    ][idx0] = v0;
            g_z2t[bb][op+100][idx0] = v1;
            if(h < 40){
                g_z2t[bb][op    ][idx1] = make_float2(sg*v0.x, -sg*v0.y);
                g_z2t[bb][op+100][idx1] = make_float2(sg*v1.x, -sg*v1.y);
            }
        }
    }
}

// ---------------- out2: packed stages + fused final via atomics ----------------
__global__ void k_out2(const float* __restrict__ b2, const float* __restrict__ W,
                       float* __restrict__ out){
    __shared__ float2 zs[405];
    __shared__ float2 g2a[10][81];
    __shared__ float2 tma[10][5][10];
    __shared__ float  wsum[8];
    int b = blockIdx.x/200, o = blockIdx.x%200;
    int t = threadIdx.x;  // 256
    for(int idx=t; idx<405; idx+=256){
        int l = idx/81, mn = idx%81, m = mn/9-4, n = mn%9-4;
        zs[idx] = (l >= max(abs(m),abs(n))) ? g_z2t[b][o][idx] : make_float2(0.f,0.f);
    }
    float b2v = b2[o];
    __syncthreads();
    for(int idx=t; idx<410; idx+=256){
        int z3 = idx/41, mn = idx%41, mm = mn/9, nn = mn%9;
        int m = mm-4, n = nn-4;
        int l0 = max(abs(m),abs(n));
        u64 acc = 0;
        for(int l=l0;l<5;l++){
            float d = c_dinv2[l][z3][mm][nn];
            fma2(acc, pk2(d,d), *(const u64*)&zs[l*81+mn]);
        }
        float2 a = u2f(acc);
        g2a[z3][mn] = a;
        g2a[z3][80-mn] = make_float2(a.x, -a.y);
    }
    __syncthreads();
    for(int idx=t; idx<500; idx+=256){
        int z3 = idx/50, rr = idx%50, mq = rr/10, k = rr%10;
        int mm = 4+mq;
        u64 acc = 0;
        #pragma unroll
        for(int nn=0;nn<9;nn++){
            float2 v = g2a[z3][mm*9+nn];
            fma2(acc, pk2(v.x,v.x), *(const u64*)&c_tw10b[nn][k]);
            fma2(acc, pk2(v.y,v.y), *(const u64*)&c_tw10br[nn][k]);
        }
        tma[z3][mq][k] = u2f(acc);
    }
    __syncthreads();
    float psum = 0.f;
    for(int idx=t; idx<1000; idx+=256){
        int z3 = idx/100, rr = idx%100, j = rr/10, k = rr%10;
        float v = tma[z3][0][k].x;
        #pragma unroll
        for(int mq=1;mq<5;mq++){
            float2 a = tma[z3][mq][k]; float2 e = c_tw10b[4+mq][j];
            v += 2.f*(a.x*e.x - a.y*e.y);
        }
        v = fmaxf(v + b2v, 0.f);
        psum += v * c_w5[z3];
    }
    #pragma unroll
    for(int off=16; off; off>>=1) psum += __shfl_xor_sync(0xFFFFFFFFu, psum, off);
    if((t&31) == 0) wsum[t>>5] = psum;
    __syncthreads();
    if(t < 10){
        float s = 0.f;
        #pragma unroll
        for(int w=0;w<8;w++) s += wsum[w];
        atomicAdd(&out[b*10+t], s*W[t*200+o]);
    }
}

extern "C" void kernel_launch(void* const* d_in, const int* in_sizes, int n_in,
                              void* d_out, int out_size){
    const float* x  = (const float*)d_in[0];
    const float* k1 = (const float*)d_in[1];
    const float* b1 = (const float*)d_in[2];
    const float* k2 = (const float*)d_in[3];
    const float* b2 = (const float*)d_in[4];
    const float* W  = (const float*)d_in[5];
    const float* bl = (const float*)d_in[6];
    float* out = (float*)d_out;

    k_init  <<<128,256>>>(bl,out);
    k_dfts  <<<(1920+100+20000+255)/256,256>>>(x,k1,k2);
    k_FGmid <<<740,256>>>();
    k_s2fuse<<<1280,400>>>(b1);
    k_xh2T2 <<<3200,256>>>();
    k_z2    <<<410,256>>>();
    k_out2  <<<6400,256>>>(b2,W,out);
}